// round 4
// baseline (speedup 1.0000x reference)
#include <cuda_runtime.h>
#include <math.h>
#include <stdint.h>

#define NB 48
#define NC 768
#define NS 361
#define NT 64
#define SPAD 384

#define TEMP1 4.0f
#define TEMP2 5.0f
#define TEMP3 10.0f
#define EPSV  1e-8f

// ----- device scratch (no allocations allowed) -----
__device__ float g_ctxp[(size_t)NB * NC * SPAD];   // padded ctx [b][d][384]
__device__ float g_G[(size_t)NB * SPAD * SPAD];    // padded Gram [b][384][384]
__device__ float g_w1n[NB * NT];
__device__ float g_gn[NB];
__device__ float g_sn[NB];
__device__ float g_sc0[NB * NB];
__device__ float g_sims[NB * NB];                  // similarities[img][cap]

// ----- cp.async helpers -----
__device__ __forceinline__ void cpa16(void* dst_smem, const void* src) {
    uint32_t d = (uint32_t)__cvta_generic_to_shared(dst_smem);
    asm volatile("cp.async.cg.shared.global [%0], [%1], 16;\n" :: "r"(d), "l"(src));
}
__device__ __forceinline__ void cpa_commit() {
    asm volatile("cp.async.commit_group;\n");
}
__device__ __forceinline__ void cpa_wait0() {
    asm volatile("cp.async.wait_group 0;\n");
}
__device__ __forceinline__ void cpa_wait1() {
    asm volatile("cp.async.wait_group 1;\n");
}

__device__ __forceinline__ void fma8x8(float (&acc)[8][8],
                                       const float4 a0, const float4 a1,
                                       const float4 b0, const float4 b1) {
    float av[8] = {a0.x, a0.y, a0.z, a0.w, a1.x, a1.y, a1.z, a1.w};
    float bv[8] = {b0.x, b0.y, b0.z, b0.w, b1.x, b1.y, b1.z, b1.w};
#pragma unroll
    for (int i = 0; i < 8; ++i)
#pragma unroll
        for (int j = 0; j < 8; ++j)
            acc[i][j] = fmaf(av[i], bv[j], acc[i][j]);
}

// ============================================================
// Pad ctx into [b][d][384] with zero pad cols
// ============================================================
__global__ void pad_kernel(const float* __restrict__ lf) {
    size_t i = (size_t)blockIdx.x * blockDim.x + threadIdx.x;
    if (i < (size_t)NB * NC * SPAD) {
        int x = (int)(i % SPAD);
        size_t r = i / SPAD;
        g_ctxp[i] = (x < NS) ? lf[r * NS + x] : 0.f;
    }
}

// ============================================================
// Gram: G_b = ctx_b^T ctx_b, padded 384x384, symmetric blocks
// grid (6, NB), 256 threads; 128x128 tile, 8x8/thread, cp.async pipelined
// dynamic smem: 2 * 2 * 32*128 floats = 64 KB
// ============================================================
#define GRAM_SMEM_BYTES (4 * 32 * 128 * 4)

__global__ __launch_bounds__(256) void gram_kernel() {
    extern __shared__ float gsm[];
    float* At[2] = {gsm, gsm + 32 * 128};
    float* Bt[2] = {gsm + 2 * 32 * 128, gsm + 3 * 32 * 128};

    const int byA[6] = {0, 0, 0, 1, 1, 2};
    const int bxA[6] = {0, 1, 2, 1, 2, 2};
    int p = blockIdx.x, b = blockIdx.y;
    int i0 = byA[p] * 128, j0 = bxA[p] * 128;
    const float* cp = g_ctxp + (size_t)b * NC * SPAD;
    int tid = threadIdx.x;
    int ti = tid & 15, si = tid >> 4;
    int il = si * 8, jl = ti * 8;
    float acc[8][8] = {};

    // preload kc=0
    for (int i4 = tid; i4 < 1024; i4 += 256) {
        int kk = i4 >> 5, x4 = i4 & 31;
        const float* base = cp + (size_t)kk * SPAD;
        cpa16(&((float4*)At[0])[i4], base + i0 + x4 * 4);
        cpa16(&((float4*)Bt[0])[i4], base + j0 + x4 * 4);
    }
    cpa_commit();

    for (int kc = 0; kc < 24; ++kc) {
        int cur = kc & 1;
        if (kc < 23) {
            int k0 = (kc + 1) * 32;
            for (int i4 = tid; i4 < 1024; i4 += 256) {
                int kk = i4 >> 5, x4 = i4 & 31;
                const float* base = cp + (size_t)(k0 + kk) * SPAD;
                cpa16(&((float4*)At[cur ^ 1])[i4], base + i0 + x4 * 4);
                cpa16(&((float4*)Bt[cur ^ 1])[i4], base + j0 + x4 * 4);
            }
            cpa_commit();
            cpa_wait1();
        } else {
            cpa_wait0();
        }
        __syncthreads();
#pragma unroll 4
        for (int k = 0; k < 32; ++k) {
            float4 a0 = *(const float4*)&At[cur][k * 128 + il];
            float4 a1 = *(const float4*)&At[cur][k * 128 + il + 4];
            float4 b0 = *(const float4*)&Bt[cur][k * 128 + jl];
            float4 b1 = *(const float4*)&Bt[cur][k * 128 + jl + 4];
            fma8x8(acc, a0, a1, b0, b1);
        }
        __syncthreads();
    }
    float* Gb = g_G + (size_t)b * SPAD * SPAD;
#pragma unroll
    for (int ii = 0; ii < 8; ++ii) {
        int row = i0 + il + ii;
        *(float4*)&Gb[(size_t)row * SPAD + j0 + jl] =
            make_float4(acc[ii][0], acc[ii][1], acc[ii][2], acc[ii][3]);
        *(float4*)&Gb[(size_t)row * SPAD + j0 + jl + 4] =
            make_float4(acc[ii][4], acc[ii][5], acc[ii][6], acc[ii][7]);
    }
    if (i0 != j0) {
#pragma unroll
        for (int jj = 0; jj < 8; ++jj) {
            int row = j0 + jl + jj;
#pragma unroll
            for (int ii = 0; ii < 8; ++ii)
                Gb[(size_t)row * SPAD + i0 + il + ii] = acc[ii][jj];
        }
    }
}

// ============================================================
// Norms
// ============================================================
__global__ void norms_kernel(const float* __restrict__ words,
                             const float* __restrict__ gfeat,
                             const float* __restrict__ sfeat) {
    int c = blockIdx.x;
    int tid = threadIdx.x;
    float s = 0.f;
    for (int d = 0; d < NC; ++d) {
        float v = words[((size_t)c * NC + d) * NT + tid];
        s = fmaf(v, v, s);
    }
    g_w1n[c * NT + tid] = sqrtf(s);

    float a = 0.f, bb = 0.f;
    for (int d = tid; d < NC; d += 64) {
        float v = gfeat[(size_t)c * NC + d];
        float w = sfeat[(size_t)c * NC + d];
        a = fmaf(v, v, a);
        bb = fmaf(w, w, bb);
    }
#pragma unroll
    for (int o = 16; o; o >>= 1) {
        a  += __shfl_xor_sync(0xffffffffu, a, o);
        bb += __shfl_xor_sync(0xffffffffu, bb, o);
    }
    __shared__ float r[4];
    int warp = tid >> 5, lane = tid & 31;
    if (lane == 0) { r[warp] = a; r[2 + warp] = bb; }
    __syncthreads();
    if (tid == 0) {
        g_gn[c] = sqrtf(r[0] + r[1]);
        g_sn[c] = sqrtf(r[2] + r[3]);
    }
}

// ============================================================
// Global scores0
// ============================================================
__global__ void gscore_kernel(const float* __restrict__ gfeat,
                              const float* __restrict__ sfeat) {
    int i = blockIdx.x;
    int tid = threadIdx.x;
    int warp = tid >> 5, lane = tid & 31;
    for (int j = warp; j < NB; j += 8) {
        float acc = 0.f;
        for (int d = lane; d < NC; d += 32)
            acc = fmaf(gfeat[(size_t)i * NC + d], sfeat[(size_t)j * NC + d], acc);
#pragma unroll
        for (int o = 16; o; o >>= 1) acc += __shfl_xor_sync(0xffffffffu, acc, o);
        if (lane == 0) {
            float denom = fmaxf(g_gn[i] * g_sn[j], EPSV);
            g_sc0[i * NB + j] = TEMP3 * acc / denom;
        }
    }
}

// ============================================================
// Per-pair kernel: one CTA per (cap c, img b); 384 threads.
// smem: buf[384*64] | ctile[2][32*384] | wtile[2][32*64] | red | red2 | misc
// ============================================================
#define SMEM_FLOATS (SPAD * NT + 2 * 32 * SPAD + 2 * 32 * NT + 3072 + 768 + 64 + 64)
#define SMEM_BYTES  (SMEM_FLOATS * 4)

__global__ __launch_bounds__(384, 1) void pair_kernel(
    const float* __restrict__ words,     // [B,C,T]
    const int*   __restrict__ cap_lens,
    float*       __restrict__ att_out,
    int write_att) {
    extern __shared__ float smem[];
    float* buf    = smem;                          // 24576 (scores -> a2u)
    float* ct0    = buf + SPAD * NT;               // 12288
    float* ct1    = ct0 + 32 * SPAD;               // 12288
    float* wt0    = ct1 + 32 * SPAD;               // 2048
    float* wt1    = wt0 + 32 * NT;                 // 2048
    float* red    = wt1 + 32 * NT;                 // 3072
    float* red2   = red + 3072;                    // 768
    float* colinv = red2 + 768;                    // 64
    float* w12s   = colinv + 64;                   // 64
    float* ct[2]  = {ct0, ct1};
    float* wt[2]  = {wt0, wt1};

    int tid = threadIdx.x;
    int bidx = blockIdx.x;
    int b = bidx % NB;        // image
    int c = bidx / NB;        // caption
    const float* cpx = g_ctxp + (size_t)b * NC * SPAD;
    const float* wrd = words + (size_t)c * NC * NT;
    const float* Gb  = g_G + (size_t)b * SPAD * SPAD;

    int sg = tid >> 3;            // 0..47
    int tg = tid & 7;             // 0..7
    int s0l = sg * 8, t0 = tg * 8;

    // ---------- Phase 1: scores[s][t], 8x8/thread, cp.async pipelined ----------
    {
        float acc[8][8] = {};
        // preload kc=0
        for (int i4 = tid; i4 < 3072; i4 += 384) {
            int kk = i4 / 96, x4 = i4 - kk * 96;
            cpa16(&((float4*)ct[0])[i4], cpx + (size_t)kk * SPAD + x4 * 4);
        }
        for (int i4 = tid; i4 < 512; i4 += 384) {
            int kk = i4 >> 4, x4 = i4 & 15;
            cpa16(&((float4*)wt[0])[i4], wrd + (size_t)kk * NT + x4 * 4);
        }
        cpa_commit();

        for (int kc = 0; kc < 24; ++kc) {
            int cur = kc & 1;
            if (kc < 23) {
                int k0 = (kc + 1) * 32;
                for (int i4 = tid; i4 < 3072; i4 += 384) {
                    int kk = i4 / 96, x4 = i4 - kk * 96;
                    cpa16(&((float4*)ct[cur ^ 1])[i4],
                          cpx + (size_t)(k0 + kk) * SPAD + x4 * 4);
                }
                for (int i4 = tid; i4 < 512; i4 += 384) {
                    int kk = i4 >> 4, x4 = i4 & 15;
                    cpa16(&((float4*)wt[cur ^ 1])[i4],
                          wrd + (size_t)(k0 + kk) * NT + x4 * 4);
                }
                cpa_commit();
                cpa_wait1();
            } else {
                cpa_wait0();
            }
            __syncthreads();
            float* cc = ct[cur];
            float* ww = wt[cur];
#pragma unroll 4
            for (int k = 0; k < 32; ++k) {
                float4 a0 = *(const float4*)&cc[k * SPAD + s0l];
                float4 a1 = *(const float4*)&cc[k * SPAD + s0l + 4];
                float4 b0 = *(const float4*)&ww[k * NT + t0];
                float4 b1 = *(const float4*)&ww[k * NT + t0 + 4];
                fma8x8(acc, a0, a1, b0, b1);
            }
            __syncthreads();
        }
#pragma unroll
        for (int ii = 0; ii < 8; ++ii) {
            *(float4*)&buf[(s0l + ii) * NT + t0] =
                make_float4(acc[ii][0], acc[ii][1], acc[ii][2], acc[ii][3]);
            *(float4*)&buf[(s0l + ii) * NT + t0 + 4] =
                make_float4(acc[ii][4], acc[ii][5], acc[ii][6], acc[ii][7]);
        }
    }
    __syncthreads();

    // Prefetch first Gram tile while we do the softmax/reductions (hidden)
    for (int i4 = tid; i4 < 3072; i4 += 384) {
        int kk = i4 / 96, x4 = i4 - kk * 96;
        cpa16(&((float4*)ct[0])[i4], Gb + (size_t)kk * SPAD + x4 * 4);
    }
    cpa_commit();

    // ---------- Phase 2: row softmax over t -> a2u; accumulate colsum & w12 ----------
    int warp = tid >> 5, lane = tid & 31;
    int cap = cap_lens[c];
    {
        float ps0 = 0.f, ps1 = 0.f, pw0 = 0.f, pw1 = 0.f;
        for (int s = warp; s < NS; s += 12) {
            float v0 = buf[s * 64 + lane];
            float v1 = buf[s * 64 + 32 + lane];
            float m0 = (lane < cap) ? v0 : -1e30f;
            float m1 = (lane + 32 < cap) ? v1 : -1e30f;
            float mx = fmaxf(m0, m1);
#pragma unroll
            for (int o = 16; o; o >>= 1)
                mx = fmaxf(mx, __shfl_xor_sync(0xffffffffu, mx, o));
            float e0 = (lane < cap) ? __expf(v0 - mx) : 0.f;
            float e1 = (lane + 32 < cap) ? __expf(v1 - mx) : 0.f;
            float sm = e0 + e1;
#pragma unroll
            for (int o = 16; o; o >>= 1)
                sm += __shfl_xor_sync(0xffffffffu, sm, o);
            float inv = 1.f / sm;
            float u0 = __expf(TEMP1 * (e0 * inv));
            float u1 = __expf(TEMP1 * (e1 * inv));
            buf[s * 64 + lane] = u0;
            buf[s * 64 + 32 + lane] = u1;
            ps0 += u0; ps1 += u1;
            pw0 = fmaf(u0, v0, pw0);
            pw1 = fmaf(u1, v1, pw1);
        }
        red[warp * 64 + lane] = ps0;
        red[warp * 64 + 32 + lane] = ps1;
        red2[warp * 64 + lane] = pw0;
        red2[warp * 64 + 32 + lane] = pw1;
        // zero pad rows 361..383
        for (int i = tid; i < (SPAD - NS) * NT; i += 384)
            buf[NS * NT + i] = 0.f;
    }
    __syncthreads();
    if (tid < 64) {
        float cs = 0.f, wsum = 0.f;
#pragma unroll
        for (int w = 0; w < 12; ++w) {
            cs += red[w * 64 + tid];
            wsum += red2[w * 64 + tid];
        }
        float ci = 1.f / cs;
        colinv[tid] = ci;
        w12s[tid] = wsum * ci;
    }

    // ---------- Phase 5: w2raw[t] = a2u^T G_b a2u, pipelined GEMM + contraction ----
    float wacc[8] = {};
    {
        float acc[8][8] = {};
        for (int kc = 0; kc < 12; ++kc) {
            int cur = kc & 1;
            if (kc < 11) {
                int k0 = (kc + 1) * 32;
                for (int i4 = tid; i4 < 3072; i4 += 384) {
                    int kk = i4 / 96, x4 = i4 - kk * 96;
                    cpa16(&((float4*)ct[cur ^ 1])[i4],
                          Gb + (size_t)(k0 + kk) * SPAD + x4 * 4);
                }
                cpa_commit();
                cpa_wait1();
            } else {
                cpa_wait0();
            }
            __syncthreads();
            float* cc = ct[cur];
            int k0 = kc * 32;
#pragma unroll 4
            for (int k = 0; k < 32; ++k) {
                float4 a0 = *(const float4*)&cc[k * SPAD + s0l];
                float4 a1 = *(const float4*)&cc[k * SPAD + s0l + 4];
                float4 b0 = *(const float4*)&buf[(k0 + k) * NT + t0];
                float4 b1 = *(const float4*)&buf[(k0 + k) * NT + t0 + 4];
                fma8x8(acc, a0, a1, b0, b1);
            }
            __syncthreads();
        }
#pragma unroll
        for (int ii = 0; ii < 8; ++ii) {
            float4 av0 = *(const float4*)&buf[(s0l + ii) * NT + t0];
            float4 av1 = *(const float4*)&buf[(s0l + ii) * NT + t0 + 4];
            wacc[0] = fmaf(av0.x, acc[ii][0], wacc[0]);
            wacc[1] = fmaf(av0.y, acc[ii][1], wacc[1]);
            wacc[2] = fmaf(av0.z, acc[ii][2], wacc[2]);
            wacc[3] = fmaf(av0.w, acc[ii][3], wacc[3]);
            wacc[4] = fmaf(av1.x, acc[ii][4], wacc[4]);
            wacc[5] = fmaf(av1.y, acc[ii][5], wacc[5]);
            wacc[6] = fmaf(av1.z, acc[ii][6], wacc[6]);
            wacc[7] = fmaf(av1.w, acc[ii][7], wacc[7]);
        }
    }
    __syncthreads();
    *(float4*)&red[sg * 64 + t0] = make_float4(wacc[0], wacc[1], wacc[2], wacc[3]);
    *(float4*)&red[sg * 64 + t0 + 4] = make_float4(wacc[4], wacc[5], wacc[6], wacc[7]);
    __syncthreads();

    // ---------- Phase 6: similarity row ----------
    if (tid < 64) {
        float w2r = 0.f;
#pragma unroll
        for (int g = 0; g < 48; ++g) w2r += red[g * 64 + tid];
        float w2 = colinv[tid] * sqrtf(w2r);
        float w1 = g_w1n[c * NT + tid];
        float sim = w12s[tid] / fmaxf(w1 * w2, EPSV);
        red2[tid] = (tid < cap) ? __expf(TEMP2 * sim) : 0.f;
    }
    __syncthreads();
    if (tid == 0) {
        float sum = 0.f;
        for (int t = 0; t < NT; ++t) sum += red2[t];
        g_sims[b * NB + c] = TEMP3 * logf(sum);
    }

    // ---------- Phase 7: att_maps for diagonal pairs ----------
    if (write_att && b == c) {
        float* ao = att_out + (size_t)b * NT * NS;
        for (int i = tid; i < NS * NT; i += 384) {
            int s = i >> 6, t = i & 63;
            ao[(size_t)t * NS + s] = buf[i] * colinv[t];
        }
    }
}

// ============================================================
// Final loss
// ============================================================
__global__ void loss_kernel(float* __restrict__ out) {
    __shared__ float part[4][NB];
    int i = threadIdx.x;
    if (i < NB) {
        const float* Ms = g_sims;
        const float* Mg = g_sc0;
        float m, sum;
        m = -INFINITY;
        for (int j = 0; j < NB; ++j) m = fmaxf(m, Ms[i * NB + j]);
        sum = 0.f;
        for (int j = 0; j < NB; ++j) sum += expf(Ms[i * NB + j] - m);
        part[0][i] = m + logf(sum) - Ms[i * NB + i];
        m = -INFINITY;
        for (int j = 0; j < NB; ++j) m = fmaxf(m, Ms[j * NB + i]);
        sum = 0.f;
        for (int j = 0; j < NB; ++j) sum += expf(Ms[j * NB + i] - m);
        part[1][i] = m + logf(sum) - Ms[i * NB + i];
        m = -INFINITY;
        for (int j = 0; j < NB; ++j) m = fmaxf(m, Mg[i * NB + j]);
        sum = 0.f;
        for (int j = 0; j < NB; ++j) sum += expf(Mg[i * NB + j] - m);
        part[2][i] = m + logf(sum) - Mg[i * NB + i];
        m = -INFINITY;
        for (int j = 0; j < NB; ++j) m = fmaxf(m, Mg[j * NB + i]);
        sum = 0.f;
        for (int j = 0; j < NB; ++j) sum += expf(Mg[j * NB + i] - m);
        part[3][i] = m + logf(sum) - Mg[i * NB + i];
    }
    __syncthreads();
    if (i == 0) {
        float l = 0.f;
        for (int k = 0; k < 4; ++k) {
            float s = 0.f;
            for (int j = 0; j < NB; ++j) s += part[k][j];
            l += s * (1.f / (float)NB);
        }
        out[0] = l;
    }
}

// ============================================================
extern "C" void kernel_launch(void* const* d_in, const int* in_sizes, int n_in,
                              void* d_out, int out_size) {
    const float* gfeat  = (const float*)d_in[0];  // [48,768]
    const float* localf = (const float*)d_in[1];  // [48,768,19,19]
    const float* words  = (const float*)d_in[2];  // [48,768,64]
    const float* sfeat  = (const float*)d_in[3];  // [48,768]
    const int*   caps   = (const int*)d_in[4];    // [48]
    float* out = (float*)d_out;

    cudaFuncSetAttribute(pair_kernel, cudaFuncAttributeMaxDynamicSharedMemorySize, SMEM_BYTES);
    cudaFuncSetAttribute(gram_kernel, cudaFuncAttributeMaxDynamicSharedMemorySize, GRAM_SMEM_BYTES);

    size_t tot = (size_t)NB * NC * SPAD;
    pad_kernel<<<(unsigned)((tot + 255) / 256), 256>>>(localf);
    gram_kernel<<<dim3(6, NB), 256, GRAM_SMEM_BYTES>>>();
    norms_kernel<<<NB, 64>>>(words, gfeat, sfeat);
    gscore_kernel<<<NB, 256>>>(gfeat, sfeat);

    int wa = (out_size >= 1 + NB * NT * NS) ? 1 : 0;
    pair_kernel<<<NB * NB, 384, SMEM_BYTES>>>(words, caps, out + 1, wa);
    loss_kernel<<<1, 64>>>(out);
}

// round 5
// speedup vs baseline: 1.0639x; 1.0639x over previous
#include <cuda_runtime.h>
#include <math.h>
#include <stdint.h>

#define NB 48
#define NC 768
#define NS 361
#define NT 64
#define SPAD 384

#define TEMP1 4.0f
#define TEMP2 5.0f
#define TEMP3 10.0f
#define EPSV  1e-8f

typedef unsigned long long ull;

// ----- device scratch (no allocations allowed) -----
__device__ float g_ctxp[(size_t)NB * NC * SPAD];   // padded ctx [b][d][384]
__device__ float g_G[(size_t)NB * SPAD * SPAD];    // padded Gram [b][384][384]
__device__ float g_w1n[NB * NT];
__device__ float g_gn[NB];
__device__ float g_sn[NB];
__device__ float g_sc0[NB * NB];
__device__ float g_sims[NB * NB];                  // similarities[img][cap]

// ----- packed f32x2 helpers -----
__device__ __forceinline__ ull pack2s(float x) {
    ull r; asm("mov.b64 %0, {%1, %1};" : "=l"(r) : "f"(x)); return r;
}
__device__ __forceinline__ void ffma2(ull& d, ull a, ull b) {
    asm("fma.rn.f32x2 %0, %1, %2, %0;" : "+l"(d) : "l"(a), "l"(b));
}
__device__ __forceinline__ void unpack2(float& lo, float& hi, ull v) {
    asm("mov.b64 {%0, %1}, %2;" : "=f"(lo), "=f"(hi) : "l"(v));
}

// 8 rows (broadcast) x 8 cols (packed pairs): 8 MOV + 32 FFMA2 per k
__device__ __forceinline__ void fma8x8p(ull (&acc)[8][4],
                                        const float4 a0, const float4 a1,
                                        const ulonglong2 b01, const ulonglong2 b23) {
    float av[8] = {a0.x, a0.y, a0.z, a0.w, a1.x, a1.y, a1.z, a1.w};
    ull bp[4] = {b01.x, b01.y, b23.x, b23.y};
#pragma unroll
    for (int i = 0; i < 8; ++i) {
        ull ap = pack2s(av[i]);
        ffma2(acc[i][0], ap, bp[0]);
        ffma2(acc[i][1], ap, bp[1]);
        ffma2(acc[i][2], ap, bp[2]);
        ffma2(acc[i][3], ap, bp[3]);
    }
}

// ============================================================
// Pad ctx into [b][d][384] with zero pad cols
// ============================================================
__global__ void pad_kernel(const float* __restrict__ lf) {
    size_t i = (size_t)blockIdx.x * blockDim.x + threadIdx.x;
    if (i < (size_t)NB * NC * SPAD) {
        int x = (int)(i % SPAD);
        size_t r = i / SPAD;
        g_ctxp[i] = (x < NS) ? lf[r * NS + x] : 0.f;
    }
}

// ============================================================
// Gram: G_b = ctx_b^T ctx_b, padded 384x384, symmetric blocks
// grid (6, NB), 256 threads; 128x128 tile per block, 8x8/thread (f32x2)
// ============================================================
__global__ __launch_bounds__(256) void gram_kernel() {
    const int byA[6] = {0, 0, 0, 1, 1, 2};
    const int bxA[6] = {0, 1, 2, 1, 2, 2};
    int p = blockIdx.x, b = blockIdx.y;
    int i0 = byA[p] * 128, j0 = bxA[p] * 128;
    __shared__ float At[32 * 128];
    __shared__ float Bt[32 * 128];
    const float* cp = g_ctxp + (size_t)b * NC * SPAD;
    int tid = threadIdx.x;
    int ti = tid & 15, si = tid >> 4;
    int il = si * 8, jl = ti * 8;
    ull acc[8][4] = {};
    for (int kc = 0; kc < 24; ++kc) {
        int k0 = kc * 32;
        __syncthreads();
        for (int i4 = tid; i4 < 1024; i4 += 256) {
            int kk = i4 >> 5, x4 = i4 & 31;
            const float* base = cp + (size_t)(k0 + kk) * SPAD;
            ((float4*)At)[i4] = *(const float4*)(base + i0 + x4 * 4);
            ((float4*)Bt)[i4] = *(const float4*)(base + j0 + x4 * 4);
        }
        __syncthreads();
#pragma unroll 4
        for (int k = 0; k < 32; ++k) {
            float4 a0 = *(const float4*)&At[k * 128 + il];
            float4 a1 = *(const float4*)&At[k * 128 + il + 4];
            ulonglong2 b01 = *(const ulonglong2*)&Bt[k * 128 + jl];
            ulonglong2 b23 = *(const ulonglong2*)&Bt[k * 128 + jl + 4];
            fma8x8p(acc, a0, a1, b01, b23);
        }
    }
    // unpack to floats
    float c[8][8];
#pragma unroll
    for (int ii = 0; ii < 8; ++ii)
#pragma unroll
        for (int j = 0; j < 4; ++j)
            unpack2(c[ii][2 * j], c[ii][2 * j + 1], acc[ii][j]);

    float* Gb = g_G + (size_t)b * SPAD * SPAD;
#pragma unroll
    for (int ii = 0; ii < 8; ++ii) {
        int row = i0 + il + ii;
        *(float4*)&Gb[(size_t)row * SPAD + j0 + jl] =
            make_float4(c[ii][0], c[ii][1], c[ii][2], c[ii][3]);
        *(float4*)&Gb[(size_t)row * SPAD + j0 + jl + 4] =
            make_float4(c[ii][4], c[ii][5], c[ii][6], c[ii][7]);
    }
    if (i0 != j0) {
#pragma unroll
        for (int jj = 0; jj < 8; ++jj) {
            int row = j0 + jl + jj;
#pragma unroll
            for (int ii = 0; ii < 8; ++ii)
                Gb[(size_t)row * SPAD + i0 + il + ii] = c[ii][jj];
        }
    }
}

// ============================================================
// Norms
// ============================================================
__global__ void norms_kernel(const float* __restrict__ words,
                             const float* __restrict__ gfeat,
                             const float* __restrict__ sfeat) {
    int c = blockIdx.x;
    int tid = threadIdx.x;
    float s = 0.f;
    for (int d = 0; d < NC; ++d) {
        float v = words[((size_t)c * NC + d) * NT + tid];
        s = fmaf(v, v, s);
    }
    g_w1n[c * NT + tid] = sqrtf(s);

    float a = 0.f, bb = 0.f;
    for (int d = tid; d < NC; d += 64) {
        float v = gfeat[(size_t)c * NC + d];
        float w = sfeat[(size_t)c * NC + d];
        a = fmaf(v, v, a);
        bb = fmaf(w, w, bb);
    }
#pragma unroll
    for (int o = 16; o; o >>= 1) {
        a  += __shfl_xor_sync(0xffffffffu, a, o);
        bb += __shfl_xor_sync(0xffffffffu, bb, o);
    }
    __shared__ float r[4];
    int warp = tid >> 5, lane = tid & 31;
    if (lane == 0) { r[warp] = a; r[2 + warp] = bb; }
    __syncthreads();
    if (tid == 0) {
        g_gn[c] = sqrtf(r[0] + r[1]);
        g_sn[c] = sqrtf(r[2] + r[3]);
    }
}

// ============================================================
// Global scores0
// ============================================================
__global__ void gscore_kernel(const float* __restrict__ gfeat,
                              const float* __restrict__ sfeat) {
    int i = blockIdx.x;
    int tid = threadIdx.x;
    int warp = tid >> 5, lane = tid & 31;
    for (int j = warp; j < NB; j += 8) {
        float acc = 0.f;
        for (int d = lane; d < NC; d += 32)
            acc = fmaf(gfeat[(size_t)i * NC + d], sfeat[(size_t)j * NC + d], acc);
#pragma unroll
        for (int o = 16; o; o >>= 1) acc += __shfl_xor_sync(0xffffffffu, acc, o);
        if (lane == 0) {
            float denom = fmaxf(g_gn[i] * g_sn[j], EPSV);
            g_sc0[i * NB + j] = TEMP3 * acc / denom;
        }
    }
}

// ============================================================
// Per-pair kernel: one CTA per (cap c, img b); 384 threads.
// smem: buf[384*64] | ctile[32*384] | wtile[32*64] | red[3072] |
//       red2[768] | colinv[64] | w12s[64]
// ============================================================
#define SMEM_FLOATS (SPAD * NT + 32 * SPAD + 32 * NT + 3072 + 768 + 64 + 64)
#define SMEM_BYTES  (SMEM_FLOATS * 4)

__global__ __launch_bounds__(384, 1) void pair_kernel(
    const float* __restrict__ words,     // [B,C,T]
    const int*   __restrict__ cap_lens,
    float*       __restrict__ att_out,
    int write_att) {
    extern __shared__ float smem[];
    float* buf    = smem;                         // 24576 (scores -> a2u)
    float* ctile  = buf + SPAD * NT;              // 12288
    float* wtile  = ctile + 32 * SPAD;            // 2048
    float* red    = wtile + 32 * NT;              // 3072
    float* red2   = red + 3072;                   // 768
    float* colinv = red2 + 768;                   // 64
    float* w12s   = colinv + 64;                  // 64

    int tid = threadIdx.x;
    int bidx = blockIdx.x;
    int b = bidx % NB;        // image
    int c = bidx / NB;        // caption
    const float* cpx = g_ctxp + (size_t)b * NC * SPAD;
    const float* wrd = words + (size_t)c * NC * NT;

    int sg = tid >> 3;            // 0..47
    int tg = tid & 7;             // 0..7
    int s0l = sg * 8, t0 = tg * 8;

    // ---------- Phase 1: scores[s][t] over all 384 rows, 8x8/thread (f32x2) ----
    {
        ull acc[8][4] = {};
        for (int kc = 0; kc < 24; ++kc) {
            int k0 = kc * 32;
            __syncthreads();
            for (int i4 = tid; i4 < 3072; i4 += 384) {
                int kk = i4 / 96;
                int x4 = i4 - kk * 96;
                ((float4*)ctile)[i4] =
                    *(const float4*)(cpx + (size_t)(k0 + kk) * SPAD + x4 * 4);
            }
            for (int i4 = tid; i4 < 512; i4 += 384) {
                int kk = i4 >> 4, x4 = i4 & 15;
                ((float4*)wtile)[i4] =
                    *(const float4*)(wrd + (size_t)(k0 + kk) * NT + x4 * 4);
            }
            __syncthreads();
#pragma unroll 4
            for (int k = 0; k < 32; ++k) {
                float4 a0 = *(const float4*)&ctile[k * SPAD + s0l];
                float4 a1 = *(const float4*)&ctile[k * SPAD + s0l + 4];
                ulonglong2 b01 = *(const ulonglong2*)&wtile[k * NT + t0];
                ulonglong2 b23 = *(const ulonglong2*)&wtile[k * NT + t0 + 4];
                fma8x8p(acc, a0, a1, b01, b23);
            }
        }
        // store packed pairs directly (lo -> t0+2j, hi -> t0+2j+1)
#pragma unroll
        for (int ii = 0; ii < 8; ++ii) {
            ulonglong2 v0, v1;
            v0.x = acc[ii][0]; v0.y = acc[ii][1];
            v1.x = acc[ii][2]; v1.y = acc[ii][3];
            *(ulonglong2*)&buf[(s0l + ii) * NT + t0] = v0;
            *(ulonglong2*)&buf[(s0l + ii) * NT + t0 + 4] = v1;
        }
    }
    __syncthreads();

    // ---------- Phase 2: row softmax over t -> a2u; accumulate colsum & w12 ----------
    int warp = tid >> 5, lane = tid & 31;
    int cap = cap_lens[c];
    {
        float ps0 = 0.f, ps1 = 0.f, pw0 = 0.f, pw1 = 0.f;
        for (int s = warp; s < NS; s += 12) {
            float v0 = buf[s * 64 + lane];
            float v1 = buf[s * 64 + 32 + lane];
            float m0 = (lane < cap) ? v0 : -1e30f;
            float m1 = (lane + 32 < cap) ? v1 : -1e30f;
            float mx = fmaxf(m0, m1);
#pragma unroll
            for (int o = 16; o; o >>= 1)
                mx = fmaxf(mx, __shfl_xor_sync(0xffffffffu, mx, o));
            float e0 = (lane < cap) ? __expf(v0 - mx) : 0.f;
            float e1 = (lane + 32 < cap) ? __expf(v1 - mx) : 0.f;
            float sm = e0 + e1;
#pragma unroll
            for (int o = 16; o; o >>= 1)
                sm += __shfl_xor_sync(0xffffffffu, sm, o);
            float inv = 1.f / sm;
            float u0 = __expf(TEMP1 * (e0 * inv));
            float u1 = __expf(TEMP1 * (e1 * inv));
            buf[s * 64 + lane] = u0;
            buf[s * 64 + 32 + lane] = u1;
            ps0 += u0; ps1 += u1;
            pw0 = fmaf(u0, v0, pw0);
            pw1 = fmaf(u1, v1, pw1);
        }
        red[warp * 64 + lane] = ps0;
        red[warp * 64 + 32 + lane] = ps1;
        red2[warp * 64 + lane] = pw0;
        red2[warp * 64 + 32 + lane] = pw1;
        // zero pad rows 361..383
        for (int i = tid; i < (SPAD - NS) * NT; i += 384)
            buf[NS * NT + i] = 0.f;
    }
    __syncthreads();
    if (tid < 64) {
        float cs = 0.f, wsum = 0.f;
#pragma unroll
        for (int w = 0; w < 12; ++w) {
            cs += red[w * 64 + tid];
            wsum += red2[w * 64 + tid];
        }
        float ci = 1.f / cs;
        colinv[tid] = ci;
        w12s[tid] = wsum * ci;
    }

    // ---------- Phase 5: w2raw[t] = a2u^T G_b a2u (f32x2 GEMM + contraction) ----
    float wacc[8] = {};
    {
        ull acc[8][4] = {};
        const float* Gb = g_G + (size_t)b * SPAD * SPAD;
        for (int kc = 0; kc < 12; ++kc) {
            int k0 = kc * 32;
            __syncthreads();
            for (int i4 = tid; i4 < 3072; i4 += 384) {
                int kk = i4 / 96;
                int x4 = i4 - kk * 96;
                ((float4*)ctile)[i4] =
                    *(const float4*)(Gb + (size_t)(k0 + kk) * SPAD + x4 * 4);
            }
            __syncthreads();
#pragma unroll 4
            for (int k = 0; k < 32; ++k) {
                float4 a0 = *(const float4*)&ctile[k * SPAD + s0l];
                float4 a1 = *(const float4*)&ctile[k * SPAD + s0l + 4];
                ulonglong2 b01 = *(const ulonglong2*)&buf[(k0 + k) * NT + t0];
                ulonglong2 b23 = *(const ulonglong2*)&buf[(k0 + k) * NT + t0 + 4];
                fma8x8p(acc, a0, a1, b01, b23);
            }
        }
#pragma unroll
        for (int ii = 0; ii < 8; ++ii) {
            float cf[8];
#pragma unroll
            for (int j = 0; j < 4; ++j)
                unpack2(cf[2 * j], cf[2 * j + 1], acc[ii][j]);
            float4 av0 = *(const float4*)&buf[(s0l + ii) * NT + t0];
            float4 av1 = *(const float4*)&buf[(s0l + ii) * NT + t0 + 4];
            wacc[0] = fmaf(av0.x, cf[0], wacc[0]);
            wacc[1] = fmaf(av0.y, cf[1], wacc[1]);
            wacc[2] = fmaf(av0.z, cf[2], wacc[2]);
            wacc[3] = fmaf(av0.w, cf[3], wacc[3]);
            wacc[4] = fmaf(av1.x, cf[4], wacc[4]);
            wacc[5] = fmaf(av1.y, cf[5], wacc[5]);
            wacc[6] = fmaf(av1.z, cf[6], wacc[6]);
            wacc[7] = fmaf(av1.w, cf[7], wacc[7]);
        }
    }
    __syncthreads();
    *(float4*)&red[sg * 64 + t0] = make_float4(wacc[0], wacc[1], wacc[2], wacc[3]);
    *(float4*)&red[sg * 64 + t0 + 4] = make_float4(wacc[4], wacc[5], wacc[6], wacc[7]);
    __syncthreads();

    // ---------- Phase 6: similarity row ----------
    if (tid < 64) {
        float w2r = 0.f;
#pragma unroll
        for (int g = 0; g < 48; ++g) w2r += red[g * 64 + tid];
        float w2 = colinv[tid] * sqrtf(w2r);
        float w1 = g_w1n[c * NT + tid];
        float sim = w12s[tid] / fmaxf(w1 * w2, EPSV);
        red2[tid] = (tid < cap) ? __expf(TEMP2 * sim) : 0.f;
    }
    __syncthreads();
    if (tid == 0) {
        float sum = 0.f;
        for (int t = 0; t < NT; ++t) sum += red2[t];
        g_sims[b * NB + c] = TEMP3 * logf(sum);
    }

    // ---------- Phase 7: att_maps for diagonal pairs ----------
    if (write_att && b == c) {
        float* ao = att_out + (size_t)b * NT * NS;
        for (int i = tid; i < NS * NT; i += 384) {
            int s = i >> 6, t = i & 63;
            ao[(size_t)t * NS + s] = buf[i] * colinv[t];
        }
    }
}

// ============================================================
// Final loss
// ============================================================
__global__ void loss_kernel(float* __restrict__ out) {
    __shared__ float part[4][NB];
    int i = threadIdx.x;
    if (i < NB) {
        const float* Ms = g_sims;
        const float* Mg = g_sc0;
        float m, sum;
        m = -INFINITY;
        for (int j = 0; j < NB; ++j) m = fmaxf(m, Ms[i * NB + j]);
        sum = 0.f;
        for (int j = 0; j < NB; ++j) sum += expf(Ms[i * NB + j] - m);
        part[0][i] = m + logf(sum) - Ms[i * NB + i];
        m = -INFINITY;
        for (int j = 0; j < NB; ++j) m = fmaxf(m, Ms[j * NB + i]);
        sum = 0.f;
        for (int j = 0; j < NB; ++j) sum += expf(Ms[j * NB + i] - m);
        part[1][i] = m + logf(sum) - Ms[i * NB + i];
        m = -INFINITY;
        for (int j = 0; j < NB; ++j) m = fmaxf(m, Mg[i * NB + j]);
        sum = 0.f;
        for (int j = 0; j < NB; ++j) sum += expf(Mg[i * NB + j] - m);
        part[2][i] = m + logf(sum) - Mg[i * NB + i];
        m = -INFINITY;
        for (int j = 0; j < NB; ++j) m = fmaxf(m, Mg[j * NB + i]);
        sum = 0.f;
        for (int j = 0; j < NB; ++j) sum += expf(Mg[j * NB + i] - m);
        part[3][i] = m + logf(sum) - Mg[i * NB + i];
    }
    __syncthreads();
    if (i == 0) {
        float l = 0.f;
        for (int k = 0; k < 4; ++k) {
            float s = 0.f;
            for (int j = 0; j < NB; ++j) s += part[k][j];
            l += s * (1.f / (float)NB);
        }
        out[0] = l;
    }
}

// ============================================================
extern "C" void kernel_launch(void* const* d_in, const int* in_sizes, int n_in,
                              void* d_out, int out_size) {
    const float* gfeat  = (const float*)d_in[0];  // [48,768]
    const float* localf = (const float*)d_in[1];  // [48,768,19,19]
    const float* words  = (const float*)d_in[2];  // [48,768,64]
    const float* sfeat  = (const float*)d_in[3];  // [48,768]
    const int*   caps   = (const int*)d_in[4];    // [48]
    float* out = (float*)d_out;

    cudaFuncSetAttribute(pair_kernel, cudaFuncAttributeMaxDynamicSharedMemorySize, SMEM_BYTES);

    size_t tot = (size_t)NB * NC * SPAD;
    pad_kernel<<<(unsigned)((tot + 255) / 256), 256>>>(localf);
    gram_kernel<<<dim3(6, NB), 256>>>();
    norms_kernel<<<NB, 64>>>(words, gfeat, sfeat);
    gscore_kernel<<<NB, 256>>>(gfeat, sfeat);

    int wa = (out_size >= 1 + NB * NT * NS) ? 1 : 0;
    pair_kernel<<<NB * NB, 384, SMEM_BYTES>>>(words, caps, out + 1, wa);
    loss_kernel<<<1, 64>>>(out);
}